// round 10
// baseline (speedup 1.0000x reference)
#include <cuda_runtime.h>
#include <math.h>
#include <stdint.h>

#define H 2048
#define HH (H*H)
#define TW 64                  // tile width (cols)
#define TH 16                  // tile height (rows)
#define IN_W 76                // input smem stride: cols c0-4 .. c0+71 (19 float4)
#define IN_H 20                // rows r0-2 .. r0+17
#define IN_HW (IN_H * IN_W)
#define YW 72                  // y smem stride: sc = gy - (c0-3)
#define YH 18                  // y rows: gyr = r0-1+ly, ly 0..17

__device__ __forceinline__ int dscalar(const int* p, int def) {
    return p ? p[0] : def;
}

__device__ __forceinline__ void cp_async16(uint32_t dst_smem, const void* src, int src_bytes) {
    asm volatile("cp.async.cg.shared.global [%0], [%1], 16, %2;\n"
                 :: "r"(dst_smem), "l"(src), "r"(src_bytes));
}
__device__ __forceinline__ void cp_async_commit_wait() {
    asm volatile("cp.async.commit_group;\n");
    asm volatile("cp.async.wait_group 0;\n" ::: "memory");
}

__global__ __launch_bounds__(256, 7)
void pgonet_main(const float* __restrict__ ref_speed,
                 const float* __restrict__ batch,
                 const float* __restrict__ x_tt,
                 const float* __restrict__ x_t,
                 const float* __restrict__ conv_v,
                 const float* __restrict__ conv_g,
                 const float* __restrict__ conv_b,
                 const float* __restrict__ ref_sol,
                 const int*   __restrict__ loc_x,
                 const int*   __restrict__ loc_y,
                 const int* p_bsize, const int* p_id,
                 const int* p_flag, const int* p_flag_num,
                 float* __restrict__ out, int P)
{
    __shared__ float s_in[3 * IN_HW];   // ch0=xtt ch1=xt ch2=speed
    __shared__ float s_y[YH * YW];
    __shared__ float s_W[28];
    __shared__ float s_b;

    const int tx = threadIdx.x & 15;      // 0..15 (float4 col group)
    const int ty = threadIdx.x >> 4;      // 0..15 (row)
    const int tid = threadIdx.x;
    const int r0 = blockIdx.y * TH;
    const int c0 = blockIdx.x * TW;

    const int bsize = dscalar(p_bsize, 10);
    const int ntb   = dscalar(p_flag, 1) - 1;
    const int step  = dscalar(p_flag_num, 1) - 1;
    const int i0    = ntb * bsize + step;
    const float* __restrict__ xtt_g = batch + (size_t)i0 * HH;
    const float* __restrict__ xt_g  = batch + (size_t)(i0 + 1) * HH;

    // ---- async-stage 3 x 20 x 76 floats: 3*20*19 = 1140 float4 groups ----
    uint32_t s_in_u32;
    {
        uint32_t a;
        asm("{ .reg .u64 t; cvta.to.shared.u64 t, %1; cvt.u32.u64 %0, t; }"
            : "=r"(a) : "l"(s_in));
        s_in_u32 = a;
    }
    #pragma unroll
    for (int it = 0; it < 5; it++) {
        int idx = tid + it * 256;
        if (idx < 3 * IN_H * 19) {
            int ch = idx / (IN_H * 19);
            int k  = idx - ch * (IN_H * 19);
            int lr = k / 19, lq = k - lr * 19;
            int gr = r0 - 2 + lr;
            int gc = c0 - 4 + 4 * lq;
            bool ok = (gr >= 0) && (gr < H) && (gc >= 0) && (gc + 3 < H);
            const float* p = (ch == 0) ? xtt_g : ((ch == 1) ? xt_g : ref_speed);
            const float* src = p + (ok ? ((size_t)gr * H + gc) : 0);
            uint32_t dst = s_in_u32 + 4u * (ch * IN_HW + lr * IN_W + 4 * lq);
            cp_async16(dst, src, ok ? 16 : 0);
        }
    }

    if (tid == 0) {
        float ss = 0.f;
        #pragma unroll
        for (int i = 0; i < 27; i++) { float v = conv_v[i]; ss += v * v; }
        float scale = conv_g[0] / sqrtf(ss);
        #pragma unroll
        for (int i = 0; i < 27; i++) s_W[i] = conv_v[i] * scale;
        s_b = conv_b[0];
    }

    cp_async_commit_wait();
    __syncthreads();

    const float* s_xtt = s_in;
    const float* s_xt  = s_in + IN_HW;
    const float* s_sp  = s_in + 2 * IN_HW;

    // ====== phase B (split by warp): conv on warps 0-4; copies on warps 5-7 ==
    if (tid < 160) {
        // conv, 8-wide strips: 18 rows * 9 strips = 162; threads 0,1 take 2.
        const float bconv = s_b;
        #pragma unroll
        for (int s = tid; s < YH * 9; s += 160) {
            int ly = s / 9, q = s - ly * 9;
            float acc[8];
            #pragma unroll
            for (int k = 0; k < 8; k++) acc[k] = bconv;
            #pragma unroll
            for (int ch = 0; ch < 3; ch++) {
                #pragma unroll
                for (int kh = 0; kh < 3; kh++) {
                    const float4* rp = reinterpret_cast<const float4*>(
                        s_in + ch * IN_HW + (ly + kh) * IN_W + 8 * q);
                    float4 A = rp[0], B = rp[1], C = rp[2];
                    float t[12] = {A.x, A.y, A.z, A.w, B.x, B.y, B.z, B.w,
                                   C.x, C.y, C.z, C.w};
                    float w0 = s_W[ch * 9 + kh * 3 + 0];
                    float w1 = s_W[ch * 9 + kh * 3 + 1];
                    float w2 = s_W[ch * 9 + kh * 3 + 2];
                    #pragma unroll
                    for (int k = 0; k < 8; k++) {
                        acc[k] = fmaf(w0, t[k], acc[k]);
                        acc[k] = fmaf(w1, t[k + 1], acc[k]);
                        acc[k] = fmaf(w2, t[k + 2], acc[k]);
                    }
                }
            }
            float4* yp = reinterpret_cast<float4*>(s_y + ly * YW + 8 * q);
            yp[0] = make_float4(acc[0], acc[1], acc[2], acc[3]);
            yp[1] = make_float4(acc[4], acc[5], acc[6], acc[7]);
        }
    } else {
        // planes 0,1,3,4: pure copies. 256 float4 units over 96 threads (3 passes).
        int j = tid - 160;
        #pragma unroll
        for (int k = 0; k < 3; k++) {
            int fi = j + k * 96;
            if (fi < TH * (TW / 4)) {
                int row = fi >> 4, cg = fi & 15;
                size_t g = (size_t)(r0 + row) * H + c0 + 4 * cg;
                float4 a = __ldcs(reinterpret_cast<const float4*>(x_tt + g));
                float4 b = __ldcs(reinterpret_cast<const float4*>(x_t + g));
                __stcs(reinterpret_cast<float4*>(out + g), a);
                __stcs(reinterpret_cast<float4*>(out + HH + g), b);
                __stcs(reinterpret_cast<float4*>(out + 3 * (size_t)HH + g), a);
                __stcs(reinterpret_cast<float4*>(out + 4 * (size_t)HH + g), b);
            }
        }
    }
    __syncthreads();

    // ====== merged epilogue: planes 2, 5, 6 — all 256 threads ======
    const int r = r0 + ty;
    const int cb = c0 + 4 * tx;

    float4 xtC  = *reinterpret_cast<const float4*>(s_xt  + (ty + 2) * IN_W + 4 * tx + 4);
    float4 xtU  = *reinterpret_cast<const float4*>(s_xt  + (ty + 1) * IN_W + 4 * tx + 4);
    float4 xtD  = *reinterpret_cast<const float4*>(s_xt  + (ty + 3) * IN_W + 4 * tx + 4);
    float  xtL  = s_xt[(ty + 2) * IN_W + 4 * tx + 3];
    float  xtR  = s_xt[(ty + 2) * IN_W + 4 * tx + 8];
    float4 xttC = *reinterpret_cast<const float4*>(s_xtt + (ty + 2) * IN_W + 4 * tx + 4);
    float4 spC  = *reinterpret_cast<const float4*>(s_sp  + (ty + 2) * IN_W + 4 * tx + 4);

    float yc8[8], yu8[8], yd8[8];
    {
        const float4* pc = reinterpret_cast<const float4*>(s_y + (ty + 1) * YW + 4 * tx);
        const float4* pu = reinterpret_cast<const float4*>(s_y + (ty    ) * YW + 4 * tx);
        const float4* pd = reinterpret_cast<const float4*>(s_y + (ty + 2) * YW + 4 * tx);
        float4 c0v = pc[0], c1v = pc[1];
        float4 u0v = pu[0], u1v = pu[1];
        float4 d0v = pd[0], d1v = pd[1];
        yc8[0]=c0v.x; yc8[1]=c0v.y; yc8[2]=c0v.z; yc8[3]=c0v.w;
        yc8[4]=c1v.x; yc8[5]=c1v.y; yc8[6]=c1v.z; yc8[7]=c1v.w;
        yu8[0]=u0v.x; yu8[1]=u0v.y; yu8[2]=u0v.z; yu8[3]=u0v.w;
        yu8[4]=u1v.x; yu8[5]=u1v.y; yu8[6]=u1v.z; yu8[7]=u1v.w;
        yd8[0]=d0v.x; yd8[1]=d0v.y; yd8[2]=d0v.z; yd8[3]=d0v.w;
        yd8[4]=d1v.x; yd8[5]=d1v.y; yd8[6]=d1v.z; yd8[7]=d1v.w;
    }

    float xtc[4]  = {xtC.x, xtC.y, xtC.z, xtC.w};
    float xtu[4]  = {xtU.x, xtU.y, xtU.z, xtU.w};
    float xtd[4]  = {xtD.x, xtD.y, xtD.z, xtD.w};
    float xttc[4] = {xttC.x, xttC.y, xttC.z, xttC.w};
    float spc[4]  = {spC.x, spC.y, spC.z, spC.w};

    float x7v[4], x7p[4], xt4[4];
    #pragma unroll
    for (int j = 0; j < 4; j++) {
        int c = cb + j;
        float xl = (j == 0) ? xtL : xtc[j - 1];
        float xr = (j == 3) ? xtR : xtc[j + 1];
        float ycn = yc8[j + 3];
        float yl  = yc8[j + 2];
        float yr2 = yc8[j + 4];

        float coef = spc[j] * spc[j] * 0.0025f;    // (DT/DX)^2
        float base = 2.f * xtc[j] - xttc[j];
        bool interior = (r > 0) & (r < H - 1) & (c > 0) & (c < H - 1);

        float lap = xtu[j] + xtd[j] + xl + xr - 4.f * xtc[j];
        xt4[j] = interior ? (base + lap * coef) : 0.f;

        float lapy = yu8[j + 3] + yd8[j + 3] + yl + yr2 - 4.f * ycn;
        float p = interior ? (base + lapy * coef) : ycn;
        x7p[j] = p;

        float v = p;
        if (r == 0) v = 0.f;
        if (c == 0)     v = xtc[j] - 0.05f * spc[j] * (xtc[j] - xr);   // DT/DX
        if (r >= 1 && r <= H - 2 && c == H - r)
            v = s_xt[(ty + 1) * IN_W + 4 * tx + j + 3];                // xt[r-1,c-1]
        if (c == H - 1) v = xtc[j] - 0.05f * spc[j] * (xtc[j] - xl);
        if (r == H - 1) v = 0.f;
        x7v[j] = v;
    }

    size_t g = (size_t)r * H + cb;
    __stcs(reinterpret_cast<float4*>(out + 2 * (size_t)HH + g),
           *reinterpret_cast<float4*>(x7v));
    __stcs(reinterpret_cast<float4*>(out + 5 * (size_t)HH + g),
           *reinterpret_cast<float4*>(x7p));
    __stcs(reinterpret_cast<float4*>(out + 6 * (size_t)HH + g),
           *reinterpret_cast<float4*>(xt4));

    // ---- folded observation scatter (block owning pixel overrides plane 2) ----
    __syncthreads();
    if (tid < P) {
        int lx = loc_x[tid];
        if (lx != -1) {
            int lyv = loc_y[tid];
            if (lx >= r0 && lx < r0 + TH && lyv >= c0 && lyv < c0 + TW) {
                int id = dscalar(p_id, 1);
                size_t obs_off = (size_t)(id * bsize + step + 2) * HH;
                size_t gs = (size_t)lx * H + lyv;
                out[2 * (size_t)HH + gs] = ref_sol[obs_off + gs];
            }
        }
    }
}

extern "C" void kernel_launch(void* const* d_in, const int* in_sizes, int n_in,
                              void* d_out, int out_size)
{
    const float* ref_speed = (const float*)d_in[0];
    const float* batch     = (const float*)d_in[1];
    const float* x_tt      = (const float*)d_in[2];
    const float* x_t       = (const float*)d_in[3];
    const float* ref_sol   = (const float*)d_in[4];
    const float* conv_v    = (const float*)d_in[5];
    const float* conv_g    = (const float*)d_in[6];
    const float* conv_b    = (const float*)d_in[7];
    const int*   loc_x     = (const int*)d_in[8];
    const int*   loc_y     = (const int*)d_in[9];
    const int* p_bsize    = (n_in > 10) ? (const int*)d_in[10] : nullptr;
    const int* p_id       = (n_in > 11) ? (const int*)d_in[11] : nullptr;
    const int* p_flag     = (n_in > 12) ? (const int*)d_in[12] : nullptr;
    const int* p_flag_num = (n_in > 13) ? (const int*)d_in[13] : nullptr;

    float* out = (float*)d_out;
    int P = in_sizes[8];

    dim3 block(256);
    dim3 grid(H / TW, H / TH);
    pgonet_main<<<grid, block>>>(ref_speed, batch, x_tt, x_t,
                                 conv_v, conv_g, conv_b,
                                 ref_sol, loc_x, loc_y,
                                 p_bsize, p_id, p_flag, p_flag_num,
                                 out, P);
}

// round 11
// speedup vs baseline: 1.3012x; 1.3012x over previous
#include <cuda_runtime.h>
#include <math.h>
#include <stdint.h>

#define H 2048
#define HH (H*H)
#define TW 64                  // tile width (cols)
#define TH 16                  // tile height (rows)
#define IN_W 76                // input smem stride: cols c0-4 .. c0+71 (19 float4)
#define IN_H 20                // rows r0-2 .. r0+17
#define IN_HW (IN_H * IN_W)
#define YW 72                  // y smem stride: sc = (gy-c0) + 3
#define YH 18                  // y rows: gyr = r0-1+ly, ly 0..17

__device__ __forceinline__ int dscalar(const int* p, int def) {
    return p ? p[0] : def;
}

__device__ __forceinline__ void cp_async16(uint32_t dst_smem, const void* src, int src_bytes) {
    asm volatile("cp.async.cg.shared.global [%0], [%1], 16, %2;\n"
                 :: "r"(dst_smem), "l"(src), "r"(src_bytes));
}
__device__ __forceinline__ void cp_async_commit_wait() {
    asm volatile("cp.async.commit_group;\n");
    asm volatile("cp.async.wait_group 0;\n" ::: "memory");
}

__global__ __launch_bounds__(256, 6)
void pgonet_main(const float* __restrict__ ref_speed,
                 const float* __restrict__ batch,
                 const float* __restrict__ x_tt,
                 const float* __restrict__ x_t,
                 const float* __restrict__ conv_v,
                 const float* __restrict__ conv_g,
                 const float* __restrict__ conv_b,
                 const float* __restrict__ ref_sol,
                 const int*   __restrict__ loc_x,
                 const int*   __restrict__ loc_y,
                 const int* p_bsize, const int* p_id,
                 const int* p_flag, const int* p_flag_num,
                 float* __restrict__ out, int P)
{
    __shared__ float s_in[3 * IN_HW];   // ch0=xtt ch1=xt ch2=speed
    __shared__ float s_y[YH * YW];
    __shared__ float s_W[28];
    __shared__ float s_b;

    const int tx = threadIdx.x & 15;      // 0..15 (float4 col group)
    const int ty = threadIdx.x >> 4;      // 0..15 (row)
    const int tid = threadIdx.x;
    const int r0 = blockIdx.y * TH;
    const int c0 = blockIdx.x * TW;

    const int bsize = dscalar(p_bsize, 10);
    const int ntb   = dscalar(p_flag, 1) - 1;
    const int step  = dscalar(p_flag_num, 1) - 1;
    const int i0    = ntb * bsize + step;
    const float* __restrict__ xtt_g = batch + (size_t)i0 * HH;
    const float* __restrict__ xt_g  = batch + (size_t)(i0 + 1) * HH;

    // ---- async-stage 3 x 20 x 76 floats: 3*20*19 = 1140 float4 groups ----
    uint32_t s_in_u32;
    {
        uint32_t a;
        asm("{ .reg .u64 t; cvta.to.shared.u64 t, %1; cvt.u32.u64 %0, t; }"
            : "=r"(a) : "l"(s_in));
        s_in_u32 = a;
    }
    #pragma unroll
    for (int it = 0; it < 5; it++) {
        int idx = tid + it * 256;
        if (idx < 3 * IN_H * 19) {
            int ch = idx / (IN_H * 19);
            int k  = idx - ch * (IN_H * 19);
            int lr = k / 19, lq = k - lr * 19;
            int gr = r0 - 2 + lr;
            int gc = c0 - 4 + 4 * lq;
            bool ok = (gr >= 0) && (gr < H) && (gc >= 0) && (gc + 3 < H);
            const float* p = (ch == 0) ? xtt_g : ((ch == 1) ? xt_g : ref_speed);
            const float* src = p + (ok ? ((size_t)gr * H + gc) : 0);
            uint32_t dst = s_in_u32 + 4u * (ch * IN_HW + lr * IN_W + 4 * lq);
            cp_async16(dst, src, ok ? 16 : 0);
        }
    }

    if (tid == 0) {
        float ss = 0.f;
        #pragma unroll
        for (int i = 0; i < 27; i++) { float v = conv_v[i]; ss += v * v; }
        float scale = conv_g[0] / sqrtf(ss);
        #pragma unroll
        for (int i = 0; i < 27; i++) s_W[i] = conv_v[i] * scale;
        s_b = conv_b[0];
    }

    cp_async_commit_wait();
    __syncthreads();

    const float* s_xtt = s_in;
    const float* s_xt  = s_in + IN_HW;
    const float* s_sp  = s_in + 2 * IN_HW;

    // ====== phase B (split by warp): conv on warps 0-4; copies on warps 5-7 ==
    if (tid < 160) {
        // conv, 8-wide strips: 18 rows * 9 strips = 162; threads 0,1 take 2.
        const float bconv = s_b;
        #pragma unroll
        for (int s = tid; s < YH * 9; s += 160) {
            int ly = s / 9, q = s - ly * 9;
            float acc[8];
            #pragma unroll
            for (int k = 0; k < 8; k++) acc[k] = bconv;
            #pragma unroll
            for (int ch = 0; ch < 3; ch++) {
                #pragma unroll
                for (int kh = 0; kh < 3; kh++) {
                    const float4* rp = reinterpret_cast<const float4*>(
                        s_in + ch * IN_HW + (ly + kh) * IN_W + 8 * q);
                    float4 A = rp[0], B = rp[1], C = rp[2];
                    float t[12] = {A.x, A.y, A.z, A.w, B.x, B.y, B.z, B.w,
                                   C.x, C.y, C.z, C.w};
                    float w0 = s_W[ch * 9 + kh * 3 + 0];
                    float w1 = s_W[ch * 9 + kh * 3 + 1];
                    float w2 = s_W[ch * 9 + kh * 3 + 2];
                    #pragma unroll
                    for (int k = 0; k < 8; k++) {
                        acc[k] = fmaf(w0, t[k], acc[k]);
                        acc[k] = fmaf(w1, t[k + 1], acc[k]);
                        acc[k] = fmaf(w2, t[k + 2], acc[k]);
                    }
                }
            }
            float4* yp = reinterpret_cast<float4*>(s_y + ly * YW + 8 * q);
            yp[0] = make_float4(acc[0], acc[1], acc[2], acc[3]);
            yp[1] = make_float4(acc[4], acc[5], acc[6], acc[7]);
        }
    } else {
        // planes 0,1,3,4: pure copies. 256 float4 units over 96 threads (3 passes).
        int j = tid - 160;
        #pragma unroll
        for (int k = 0; k < 3; k++) {
            int fi = j + k * 96;
            if (fi < TH * (TW / 4)) {
                int row = fi >> 4, cg = fi & 15;
                size_t g = (size_t)(r0 + row) * H + c0 + 4 * cg;
                float4 a = __ldcs(reinterpret_cast<const float4*>(x_tt + g));
                float4 b = __ldcs(reinterpret_cast<const float4*>(x_t + g));
                __stcs(reinterpret_cast<float4*>(out + g), a);
                __stcs(reinterpret_cast<float4*>(out + HH + g), b);
                __stcs(reinterpret_cast<float4*>(out + 3 * (size_t)HH + g), a);
                __stcs(reinterpret_cast<float4*>(out + 4 * (size_t)HH + g), b);
            }
        }
    }
    __syncthreads();

    // ====== merged epilogue: planes 2, 5, 6 — all 256 threads ======
    const int r = r0 + ty;
    const int cb = c0 + 4 * tx;

    float4 xtC  = *reinterpret_cast<const float4*>(s_xt  + (ty + 2) * IN_W + 4 * tx + 4);
    float4 xtU  = *reinterpret_cast<const float4*>(s_xt  + (ty + 1) * IN_W + 4 * tx + 4);
    float4 xtD  = *reinterpret_cast<const float4*>(s_xt  + (ty + 3) * IN_W + 4 * tx + 4);
    float  xtL  = s_xt[(ty + 2) * IN_W + 4 * tx + 3];
    float  xtR  = s_xt[(ty + 2) * IN_W + 4 * tx + 8];
    float4 xttC = *reinterpret_cast<const float4*>(s_xtt + (ty + 2) * IN_W + 4 * tx + 4);
    float4 spC  = *reinterpret_cast<const float4*>(s_sp  + (ty + 2) * IN_W + 4 * tx + 4);

    // y reads: centers of rows ty (up), ty+1 (center), ty+2 (down) are at
    // sc = 4tx+3 .. 4tx+6. One aligned vec at sc=4tx+4 (m=4tx+1..4tx+4) plus
    // one scalar at sc=4tx+3 (m=4tx) per row; center row adds yl scalar at 4tx+2.
    float4 yCv = *reinterpret_cast<const float4*>(s_y + (ty + 1) * YW + 4 * tx + 4);
    float4 yUv = *reinterpret_cast<const float4*>(s_y + (ty    ) * YW + 4 * tx + 4);
    float4 yDv = *reinterpret_cast<const float4*>(s_y + (ty + 2) * YW + 4 * tx + 4);
    float  yC0 = s_y[(ty + 1) * YW + 4 * tx + 3];
    float  yCl = s_y[(ty + 1) * YW + 4 * tx + 2];
    float  yU0 = s_y[(ty    ) * YW + 4 * tx + 3];
    float  yD0 = s_y[(ty + 2) * YW + 4 * tx + 3];

    float yc_[4] = {yC0, yCv.x, yCv.y, yCv.z};
    float yu_[4] = {yU0, yUv.x, yUv.y, yUv.z};
    float yd_[4] = {yD0, yDv.x, yDv.y, yDv.z};

    float xtc[4]  = {xtC.x, xtC.y, xtC.z, xtC.w};
    float xtu[4]  = {xtU.x, xtU.y, xtU.z, xtU.w};
    float xtd[4]  = {xtD.x, xtD.y, xtD.z, xtD.w};
    float xttc[4] = {xttC.x, xttC.y, xttC.z, xttC.w};
    float spc[4]  = {spC.x, spC.y, spC.z, spC.w};

    float x7v[4], x7p[4], xt4[4];
    #pragma unroll
    for (int j = 0; j < 4; j++) {
        int c = cb + j;
        float xl = (j == 0) ? xtL : xtc[j - 1];
        float xr = (j == 3) ? xtR : xtc[j + 1];
        float ycn = yc_[j];
        float yl  = (j == 0) ? yCl : yc_[j - 1];
        float yr2 = (j == 3) ? yCv.w : yc_[j + 1];

        float coef = spc[j] * spc[j] * 0.0025f;    // (DT/DX)^2
        float base = 2.f * xtc[j] - xttc[j];
        bool interior = (r > 0) & (r < H - 1) & (c > 0) & (c < H - 1);

        float lap = xtu[j] + xtd[j] + xl + xr - 4.f * xtc[j];
        xt4[j] = interior ? (base + lap * coef) : 0.f;

        float lapy = yu_[j] + yd_[j] + yl + yr2 - 4.f * ycn;
        float p = interior ? (base + lapy * coef) : ycn;
        x7p[j] = p;

        float v = p;
        if (r == 0) v = 0.f;
        if (c == 0)     v = xtc[j] - 0.05f * spc[j] * (xtc[j] - xr);   // DT/DX
        if (r >= 1 && r <= H - 2 && c == H - r)
            v = s_xt[(ty + 1) * IN_W + 4 * tx + j + 3];                // xt[r-1,c-1]
        if (c == H - 1) v = xtc[j] - 0.05f * spc[j] * (xtc[j] - xl);
        if (r == H - 1) v = 0.f;
        x7v[j] = v;
    }

    size_t g = (size_t)r * H + cb;
    __stcs(reinterpret_cast<float4*>(out + 2 * (size_t)HH + g),
           *reinterpret_cast<float4*>(x7v));
    __stcs(reinterpret_cast<float4*>(out + 5 * (size_t)HH + g),
           *reinterpret_cast<float4*>(x7p));
    __stcs(reinterpret_cast<float4*>(out + 6 * (size_t)HH + g),
           *reinterpret_cast<float4*>(xt4));

    // ---- folded observation scatter (block owning pixel overrides plane 2) ----
    __syncthreads();
    if (tid < P) {
        int lx = loc_x[tid];
        if (lx != -1) {
            int lyv = loc_y[tid];
            if (lx >= r0 && lx < r0 + TH && lyv >= c0 && lyv < c0 + TW) {
                int id = dscalar(p_id, 1);
                size_t obs_off = (size_t)(id * bsize + step + 2) * HH;
                size_t gs = (size_t)lx * H + lyv;
                out[2 * (size_t)HH + gs] = ref_sol[obs_off + gs];
            }
        }
    }
}

extern "C" void kernel_launch(void* const* d_in, const int* in_sizes, int n_in,
                              void* d_out, int out_size)
{
    const float* ref_speed = (const float*)d_in[0];
    const float* batch     = (const float*)d_in[1];
    const float* x_tt      = (const float*)d_in[2];
    const float* x_t       = (const float*)d_in[3];
    const float* ref_sol   = (const float*)d_in[4];
    const float* conv_v    = (const float*)d_in[5];
    const float* conv_g    = (const float*)d_in[6];
    const float* conv_b    = (const float*)d_in[7];
    const int*   loc_x     = (const int*)d_in[8];
    const int*   loc_y     = (const int*)d_in[9];
    const int* p_bsize    = (n_in > 10) ? (const int*)d_in[10] : nullptr;
    const int* p_id       = (n_in > 11) ? (const int*)d_in[11] : nullptr;
    const int* p_flag     = (n_in > 12) ? (const int*)d_in[12] : nullptr;
    const int* p_flag_num = (n_in > 13) ? (const int*)d_in[13] : nullptr;

    float* out = (float*)d_out;
    int P = in_sizes[8];

    dim3 block(256);
    dim3 grid(H / TW, H / TH);
    pgonet_main<<<grid, block>>>(ref_speed, batch, x_tt, x_t,
                                 conv_v, conv_g, conv_b,
                                 ref_sol, loc_x, loc_y,
                                 p_bsize, p_id, p_flag, p_flag_num,
                                 out, P);
}

// round 12
// speedup vs baseline: 1.3450x; 1.0336x over previous
#include <cuda_runtime.h>
#include <math.h>
#include <stdint.h>

#define H 2048
#define HH (H*H)
#define TW 64                  // tile width (cols)
#define TH 16                  // tile height (rows)
#define IN_W 76                // input smem stride: cols c0-4 .. c0+71 (19 float4)
#define IN_H 20                // rows R0-2 .. R0+17
#define IN_HW (IN_H * IN_W)
#define YW 72                  // y smem stride: sc = (gy-c0) + 3
#define YH 18                  // y rows: gyr = R0-1+ly, ly 0..17

__device__ __forceinline__ int dscalar(const int* p, int def) {
    return p ? p[0] : def;
}

__device__ __forceinline__ void cp_async16(uint32_t dst_smem, const void* src, int src_bytes) {
    asm volatile("cp.async.cg.shared.global [%0], [%1], 16, %2;\n"
                 :: "r"(dst_smem), "l"(src), "r"(src_bytes));
}
__device__ __forceinline__ void cp_async_commit() {
    asm volatile("cp.async.commit_group;\n");
}
template<int N>
__device__ __forceinline__ void cp_async_wait() {
    asm volatile("cp.async.wait_group %0;\n" :: "n"(N) : "memory");
}

__global__ __launch_bounds__(256, 5)
void pgonet_main(const float* __restrict__ ref_speed,
                 const float* __restrict__ batch,
                 const float* __restrict__ x_tt,
                 const float* __restrict__ x_t,
                 const float* __restrict__ conv_v,
                 const float* __restrict__ conv_g,
                 const float* __restrict__ conv_b,
                 const float* __restrict__ ref_sol,
                 const int*   __restrict__ loc_x,
                 const int*   __restrict__ loc_y,
                 const int* p_bsize, const int* p_id,
                 const int* p_flag, const int* p_flag_num,
                 float* __restrict__ out, int P)
{
    __shared__ float s_buf[2][3 * IN_HW];   // double-buffered: xtt, xt, speed
    __shared__ float s_y[YH * YW];
    __shared__ float s_W[28];
    __shared__ float s_b;

    const int tx = threadIdx.x & 15;      // 0..15 (float4 col group)
    const int ty = threadIdx.x >> 4;      // 0..15 (row)
    const int tid = threadIdx.x;
    const int R0base = blockIdx.y * (2 * TH);   // this CTA covers 32 rows
    const int c0 = blockIdx.x * TW;

    const int bsize = dscalar(p_bsize, 10);
    const int ntb   = dscalar(p_flag, 1) - 1;
    const int step  = dscalar(p_flag_num, 1) - 1;
    const int i0    = ntb * bsize + step;
    const float* __restrict__ xtt_g = batch + (size_t)i0 * HH;
    const float* __restrict__ xt_g  = batch + (size_t)(i0 + 1) * HH;

    uint32_t s_buf_u32;
    {
        uint32_t a;
        asm("{ .reg .u64 t; cvta.to.shared.u64 t, %1; cvt.u32.u64 %0, t; }"
            : "=r"(a) : "l"(&s_buf[0][0]));
        s_buf_u32 = a;
    }

    // ---- issue staging for BOTH tiles (separate commit groups) ----
    #pragma unroll 1
    for (int b = 0; b < 2; b++) {
        int R0 = R0base + b * TH;
        #pragma unroll
        for (int it = 0; it < 5; it++) {
            int idx = tid + it * 256;
            if (idx < 3 * IN_H * 19) {
                int ch = idx / (IN_H * 19);
                int k  = idx - ch * (IN_H * 19);
                int lr = k / 19, lq = k - lr * 19;
                int gr = R0 - 2 + lr;
                int gc = c0 - 4 + 4 * lq;
                bool ok = (gr >= 0) && (gr < H) && (gc >= 0) && (gc + 3 < H);
                const float* p = (ch == 0) ? xtt_g : ((ch == 1) ? xt_g : ref_speed);
                const float* src = p + (ok ? ((size_t)gr * H + gc) : 0);
                uint32_t dst = s_buf_u32
                    + 4u * (b * 3 * IN_HW + ch * IN_HW + lr * IN_W + 4 * lq);
                cp_async16(dst, src, ok ? 16 : 0);
            }
        }
        cp_async_commit();
    }

    if (tid == 0) {
        float ss = 0.f;
        #pragma unroll
        for (int i = 0; i < 27; i++) { float v = conv_v[i]; ss += v * v; }
        float scale = conv_g[0] / sqrtf(ss);
        #pragma unroll
        for (int i = 0; i < 27; i++) s_W[i] = conv_v[i] * scale;
        s_b = conv_b[0];
    }

    cp_async_wait<1>();      // tile 0 ready; tile 1 still in flight
    __syncthreads();

    #pragma unroll 1
    for (int t = 0; t < 2; t++) {
        if (t == 1) {
            cp_async_wait<0>();   // tile 1 data ready
            __syncthreads();      // also orders epilogue-0 s_y reads before conv-1 writes
        }
        const float* s_in  = &s_buf[t][0];
        const float* s_xtt = s_in;
        const float* s_xt  = s_in + IN_HW;
        const float* s_sp  = s_in + 2 * IN_HW;
        const int r0 = R0base + t * TH;

        // ==== phase B (warp split): conv on warps 0-4; copies on warps 5-7 ====
        if (tid < 160) {
            const float bconv = s_b;
            #pragma unroll
            for (int s = tid; s < YH * 9; s += 160) {
                int ly = s / 9, q = s - ly * 9;
                float acc[8];
                #pragma unroll
                for (int k = 0; k < 8; k++) acc[k] = bconv;
                #pragma unroll
                for (int ch = 0; ch < 3; ch++) {
                    #pragma unroll
                    for (int kh = 0; kh < 3; kh++) {
                        const float4* rp = reinterpret_cast<const float4*>(
                            s_in + ch * IN_HW + (ly + kh) * IN_W + 8 * q);
                        float4 A = rp[0], B = rp[1], C = rp[2];
                        float tt[12] = {A.x, A.y, A.z, A.w, B.x, B.y, B.z, B.w,
                                        C.x, C.y, C.z, C.w};
                        float w0 = s_W[ch * 9 + kh * 3 + 0];
                        float w1 = s_W[ch * 9 + kh * 3 + 1];
                        float w2 = s_W[ch * 9 + kh * 3 + 2];
                        #pragma unroll
                        for (int k = 0; k < 8; k++) {
                            acc[k] = fmaf(w0, tt[k], acc[k]);
                            acc[k] = fmaf(w1, tt[k + 1], acc[k]);
                            acc[k] = fmaf(w2, tt[k + 2], acc[k]);
                        }
                    }
                }
                float4* yp = reinterpret_cast<float4*>(s_y + ly * YW + 8 * q);
                yp[0] = make_float4(acc[0], acc[1], acc[2], acc[3]);
                yp[1] = make_float4(acc[4], acc[5], acc[6], acc[7]);
            }
        } else {
            // planes 0,1,3,4 copies: 256 float4 over 96 threads (3 passes)
            int j = tid - 160;
            #pragma unroll
            for (int k = 0; k < 3; k++) {
                int fi = j + k * 96;
                if (fi < TH * (TW / 4)) {
                    int row = fi >> 4, cg = fi & 15;
                    size_t g = (size_t)(r0 + row) * H + c0 + 4 * cg;
                    float4 a = __ldcs(reinterpret_cast<const float4*>(x_tt + g));
                    float4 b = __ldcs(reinterpret_cast<const float4*>(x_t + g));
                    __stcs(reinterpret_cast<float4*>(out + g), a);
                    __stcs(reinterpret_cast<float4*>(out + HH + g), b);
                    __stcs(reinterpret_cast<float4*>(out + 3 * (size_t)HH + g), a);
                    __stcs(reinterpret_cast<float4*>(out + 4 * (size_t)HH + g), b);
                }
            }
        }
        __syncthreads();

        // ==== epilogue: planes 2, 5, 6 — all 256 threads ====
        const int r = r0 + ty;
        const int cb = c0 + 4 * tx;

        float4 xtC  = *reinterpret_cast<const float4*>(s_xt  + (ty + 2) * IN_W + 4 * tx + 4);
        float4 xtU  = *reinterpret_cast<const float4*>(s_xt  + (ty + 1) * IN_W + 4 * tx + 4);
        float4 xtD  = *reinterpret_cast<const float4*>(s_xt  + (ty + 3) * IN_W + 4 * tx + 4);
        float  xtL  = s_xt[(ty + 2) * IN_W + 4 * tx + 3];
        float  xtR  = s_xt[(ty + 2) * IN_W + 4 * tx + 8];
        float4 xttC = *reinterpret_cast<const float4*>(s_xtt + (ty + 2) * IN_W + 4 * tx + 4);
        float4 spC  = *reinterpret_cast<const float4*>(s_sp  + (ty + 2) * IN_W + 4 * tx + 4);

        float4 yCv = *reinterpret_cast<const float4*>(s_y + (ty + 1) * YW + 4 * tx + 4);
        float4 yUv = *reinterpret_cast<const float4*>(s_y + (ty    ) * YW + 4 * tx + 4);
        float4 yDv = *reinterpret_cast<const float4*>(s_y + (ty + 2) * YW + 4 * tx + 4);
        float  yC0 = s_y[(ty + 1) * YW + 4 * tx + 3];
        float  yCl = s_y[(ty + 1) * YW + 4 * tx + 2];
        float  yU0 = s_y[(ty    ) * YW + 4 * tx + 3];
        float  yD0 = s_y[(ty + 2) * YW + 4 * tx + 3];

        float yc_[4] = {yC0, yCv.x, yCv.y, yCv.z};
        float yu_[4] = {yU0, yUv.x, yUv.y, yUv.z};
        float yd_[4] = {yD0, yDv.x, yDv.y, yDv.z};

        float xtc[4]  = {xtC.x, xtC.y, xtC.z, xtC.w};
        float xtu[4]  = {xtU.x, xtU.y, xtU.z, xtU.w};
        float xtd[4]  = {xtD.x, xtD.y, xtD.z, xtD.w};
        float xttc[4] = {xttC.x, xttC.y, xttC.z, xttC.w};
        float spc[4]  = {spC.x, spC.y, spC.z, spC.w};

        float x7v[4], x7p[4], xt4[4];
        #pragma unroll
        for (int j = 0; j < 4; j++) {
            int c = cb + j;
            float xl = (j == 0) ? xtL : xtc[j - 1];
            float xr = (j == 3) ? xtR : xtc[j + 1];
            float ycn = yc_[j];
            float yl  = (j == 0) ? yCl : yc_[j - 1];
            float yr2 = (j == 3) ? yCv.w : yc_[j + 1];

            float coef = spc[j] * spc[j] * 0.0025f;    // (DT/DX)^2
            float base = 2.f * xtc[j] - xttc[j];
            bool interior = (r > 0) & (r < H - 1) & (c > 0) & (c < H - 1);

            float lap = xtu[j] + xtd[j] + xl + xr - 4.f * xtc[j];
            xt4[j] = interior ? (base + lap * coef) : 0.f;

            float lapy = yu_[j] + yd_[j] + yl + yr2 - 4.f * ycn;
            float p = interior ? (base + lapy * coef) : ycn;
            x7p[j] = p;

            float v = p;
            if (r == 0) v = 0.f;
            if (c == 0)     v = xtc[j] - 0.05f * spc[j] * (xtc[j] - xr);   // DT/DX
            if (r >= 1 && r <= H - 2 && c == H - r)
                v = s_xt[(ty + 1) * IN_W + 4 * tx + j + 3];                // xt[r-1,c-1]
            if (c == H - 1) v = xtc[j] - 0.05f * spc[j] * (xtc[j] - xl);
            if (r == H - 1) v = 0.f;
            x7v[j] = v;
        }

        size_t g = (size_t)r * H + cb;
        __stcs(reinterpret_cast<float4*>(out + 2 * (size_t)HH + g),
               *reinterpret_cast<float4*>(x7v));
        __stcs(reinterpret_cast<float4*>(out + 5 * (size_t)HH + g),
               *reinterpret_cast<float4*>(x7p));
        __stcs(reinterpret_cast<float4*>(out + 6 * (size_t)HH + g),
               *reinterpret_cast<float4*>(xt4));
    }

    // ---- folded observation scatter over the CTA's 32-row region ----
    __syncthreads();
    if (tid < P) {
        int lx = loc_x[tid];
        if (lx != -1) {
            int lyv = loc_y[tid];
            if (lx >= R0base && lx < R0base + 2 * TH &&
                lyv >= c0 && lyv < c0 + TW) {
                int id = dscalar(p_id, 1);
                size_t obs_off = (size_t)(id * bsize + step + 2) * HH;
                size_t gs = (size_t)lx * H + lyv;
                out[2 * (size_t)HH + gs] = ref_sol[obs_off + gs];
            }
        }
    }
}

extern "C" void kernel_launch(void* const* d_in, const int* in_sizes, int n_in,
                              void* d_out, int out_size)
{
    const float* ref_speed = (const float*)d_in[0];
    const float* batch     = (const float*)d_in[1];
    const float* x_tt      = (const float*)d_in[2];
    const float* x_t       = (const float*)d_in[3];
    const float* ref_sol   = (const float*)d_in[4];
    const float* conv_v    = (const float*)d_in[5];
    const float* conv_g    = (const float*)d_in[6];
    const float* conv_b    = (const float*)d_in[7];
    const int*   loc_x     = (const int*)d_in[8];
    const int*   loc_y     = (const int*)d_in[9];
    const int* p_bsize    = (n_in > 10) ? (const int*)d_in[10] : nullptr;
    const int* p_id       = (n_in > 11) ? (const int*)d_in[11] : nullptr;
    const int* p_flag     = (n_in > 12) ? (const int*)d_in[12] : nullptr;
    const int* p_flag_num = (n_in > 13) ? (const int*)d_in[13] : nullptr;

    float* out = (float*)d_out;
    int P = in_sizes[8];

    dim3 block(256);
    dim3 grid(H / TW, H / (2 * TH));
    pgonet_main<<<grid, block>>>(ref_speed, batch, x_tt, x_t,
                                 conv_v, conv_g, conv_b,
                                 ref_sol, loc_x, loc_y,
                                 p_bsize, p_id, p_flag, p_flag_num,
                                 out, P);
}